// round 9
// baseline (speedup 1.0000x reference)
#include <cuda_runtime.h>
#include <math.h>

// LSTM autoregressive decoder, B=256, H=1024, I=1, O=512, T=512.
// Single persistent kernel (1 graph node) with software grid barriers.
// fp32 throughout (argmax feedback makes low precision catastrophic).
// c lives in registers; h double-buffered in __device__ globals (ldcg reads).

#define BATCH  256
#define HID    1024
#define OUTF   512
#define TSTEPS 512
#define NBLK   128
#define NTHR   256

__device__ __align__(16) float g_h[2][BATCH * HID];
__device__ unsigned long long g_part[BATCH][2];  // per (row, o-half) packed argmax
__device__ int g_count;        // zero-init; barrier releaser restores to 0
__device__ unsigned g_sense;   // read dynamically at launch start

__device__ __forceinline__ void gridbar(unsigned sense_val) {
    __threadfence();           // every thread fences its own global stores
    __syncthreads();           // all fences done before block arrives
    if (threadIdx.x == 0) {
        if (atomicAdd(&g_count, 1) == NBLK - 1) {
            atomicExch(&g_count, 0);     // reset BEFORE release
            __threadfence();
            atomicExch(&g_sense, sense_val ^ 1);
        } else {
            while (*(volatile unsigned*)&g_sense == sense_val) __nanosleep(32);
        }
    }
    __syncthreads();
}

__device__ __forceinline__ float sigf(float x) {
    return 1.f / (1.f + expf(-x));
}

__global__ __launch_bounds__(NTHR, 1)
void lstm_persistent(const float* __restrict__ z,
                     const float* __restrict__ w_ih,
                     const float* __restrict__ w_hh,
                     const float* __restrict__ b_ih,
                     const float* __restrict__ b_hh,
                     const float* __restrict__ w_lin,
                     const float* __restrict__ b_lin,
                     float* __restrict__ out)
{
    // 16 KB pool, triple-aliased (all uses are exactly 4096 floats):
    //  phase A GEMM:   h_s  [32 batch][128 k]
    //  phase A gates:  gbuf [16 batch][256 gate-j]   (h_s dead by then)
    //  phase B GEMM:   hrow [4 batch][1024 k]
    __shared__ __align__(16) float pool[4096];
    __shared__ float xin_s[32];
    __shared__ unsigned long long kbuf[4][8];

    const int blk = blockIdx.x;
    const int t   = threadIdx.x;

    // ---- phase A (gates GEMM + cell) indices: 16 j-tiles x 8 batch-tiles ----
    const int bxA = blk & 15;            // j tile (64 hidden each)
    const int b0A = (blk >> 4) << 5;     // batch tile base (32 rows)
    const int gA  = t >> 6;              // gate 0..3 (i,f,g,o)
    const int jA  = t & 63;
    const int rowA = (gA << 10) + (bxA << 6) + jA;   // row in [4H, H]
    const float* __restrict__ wrowA = w_hh + (size_t)rowA * HID;
    const float biasA = b_ih[rowA] + b_hh[rowA];
    const float wihA  = w_ih[rowA];      // I == 1

    // ---- phase B (head GEMM + argmax) indices: 2 o-halves x 64 batch-tiles --
    const int ohalf = blk & 1;
    const int b0B   = (blk >> 1) << 2;   // 4 batch rows
    const int oB    = (ohalf << 8) + t;  // output index 0..511
    const float* __restrict__ wrowB = w_lin + (size_t)oB * HID;
    const float blB = b_lin[oB];

    float c_reg[8];                      // cell state: fixed (b,j) per thread
#pragma unroll
    for (int r = 0; r < 8; r++) c_reg[r] = 0.f;

    unsigned sense = *(volatile unsigned*)&g_sense;   // safe: no flip before all arrive

    for (int s = 0; s < TSTEPS; s++) {
        const float* __restrict__ hin = (s == 0) ? z : g_h[(s + 1) & 1];
        float* __restrict__ hout = g_h[s & 1];

        // ---------------- Phase A: gates GEMM + LSTM cell ----------------
        // xin for this block's 32 batch rows from last step's argmax partials
        if (t < 32) {
            float x = 0.f;
            if (s > 0) {
                unsigned long long k0 = __ldcg(&g_part[b0A + t][0]);
                unsigned long long k1 = __ldcg(&g_part[b0A + t][1]);
                unsigned long long k  = (k1 > k0) ? k1 : k0;   // val max, min idx on tie
                x = (float)(0xFFFFFFFFu - (unsigned)(k & 0xFFFFFFFFull));
            }
            xin_s[t] = x;
        }
        // (first kc-loop __syncthreads orders xin_s writes before any read)

        float acc[32];
#pragma unroll
        for (int b = 0; b < 32; b++) acc[b] = 0.f;

        for (int kc = 0; kc < HID; kc += 128) {
            __syncthreads();
            {   // stage h tile: 32 rows x 128 cols = 1024 float4
                int i = t;
#pragma unroll
                for (int r = 0; r < 4; r++, i += 256) {
                    int bb = i >> 5, kk = (i & 31) << 2;
                    float4 v = __ldcg((const float4*)(hin + (size_t)(b0A + bb) * HID + kc + kk));
                    *(float4*)&pool[bb * 128 + kk] = v;
                }
            }
            __syncthreads();

#pragma unroll 4
            for (int kk = 0; kk < 128; kk += 4) {
                float4 w = *(const float4*)(wrowA + kc + kk);
#pragma unroll
                for (int b = 0; b < 32; b++) {
                    float4 hv = *(const float4*)&pool[b * 128 + kk];  // broadcast
                    acc[b] = fmaf(w.x, hv.x, acc[b]);
                    acc[b] = fmaf(w.y, hv.y, acc[b]);
                    acc[b] = fmaf(w.z, hv.z, acc[b]);
                    acc[b] = fmaf(w.w, hv.w, acc[b]);
                }
            }
        }

        // Gate recombine + cell update, 16 batch rows at a time (gbuf = 16 KB)
#pragma unroll
        for (int half = 0; half < 2; half++) {
            __syncthreads();                          // h_s / previous gbuf dead
#pragma unroll
            for (int b = 0; b < 16; b++) {
                int bb = half * 16 + b;
                pool[b * 256 + t] = acc[bb] + biasA + xin_s[bb] * wihA;
            }
            __syncthreads();
#pragma unroll
            for (int r = 0; r < 4; r++) {
                int id = (r << 8) + t;                // 0..1023 = bb*64 + jj
                int jj = id & 63, bb = id >> 6;
                float gi = pool[bb * 256 +       jj];
                float gf = pool[bb * 256 +  64 + jj];
                float gg = pool[bb * 256 + 128 + jj];
                float go = pool[bb * 256 + 192 + jj];
                int ci = half * 4 + r;
                float cn = sigf(gf) * c_reg[ci] + sigf(gi) * tanhf(gg);
                float hn = sigf(go) * tanhf(cn);
                c_reg[ci] = cn;
                hout[(size_t)(b0A + half * 16 + bb) * HID + (bxA << 6) + jj] = hn;
            }
        }

        gridbar(sense); sense ^= 1;    // barrier 1: h_new visible everywhere

        // ---------------- Phase B: head GEMM + logits + argmax ----------------
        {   // stage 4 h rows (4 x 1024 floats) into pool
            int i = t;
#pragma unroll
            for (int r = 0; r < 4; r++, i += 256) {
                int bb = i >> 8, kk = (i & 255) << 2;
                *(float4*)&pool[bb * 1024 + kk] =
                    __ldcg((const float4*)(hout + (size_t)(b0B + bb) * HID + kk));
            }
        }
        __syncthreads();

        float acc4[4] = {0.f, 0.f, 0.f, 0.f};
#pragma unroll 4
        for (int k = 0; k < HID; k += 4) {
            float4 w = *(const float4*)(wrowB + k);
#pragma unroll
            for (int b = 0; b < 4; b++) {
                float4 hv = *(const float4*)&pool[b * 1024 + k];
                acc4[b] = fmaf(w.x, hv.x, acc4[b]);
                acc4[b] = fmaf(w.y, hv.y, acc4[b]);
                acc4[b] = fmaf(w.z, hv.z, acc4[b]);
                acc4[b] = fmaf(w.w, hv.w, acc4[b]);
            }
        }

        unsigned long long bkey[4];
#pragma unroll
        for (int b = 0; b < 4; b++) {
            float v = acc4[b] + blB;
            out[(size_t)(b0B + b) * TSTEPS * OUTF + (size_t)s * OUTF + oB] = v;
            unsigned u = __float_as_uint(v);
            u = (u & 0x80000000u) ? ~u : (u | 0x80000000u);   // order-preserving
            // max key => max val; on equal val, max(0xFFFFFFFF - o) => min o (jnp first-max)
            bkey[b] = ((unsigned long long)u << 32) | (unsigned long long)(0xFFFFFFFFu - (unsigned)oB);
        }
#pragma unroll
        for (int b = 0; b < 4; b++) {
            unsigned long long k = bkey[b];
#pragma unroll
            for (int off = 16; off; off >>= 1) {
                unsigned long long ok = __shfl_xor_sync(0xffffffffu, k, off);
                if (ok > k) k = ok;
            }
            bkey[b] = k;
        }
        if ((t & 31) == 0) {
            int w = t >> 5;
#pragma unroll
            for (int b = 0; b < 4; b++) kbuf[b][w] = bkey[b];
        }
        __syncthreads();
        if (t < 4) {
            unsigned long long k = kbuf[t][0];
#pragma unroll
            for (int w = 1; w < 8; w++) if (kbuf[t][w] > k) k = kbuf[t][w];
            g_part[b0B + t][ohalf] = k;
        }

        gridbar(sense); sense ^= 1;    // barrier 2: argmax partials visible
    }
}

extern "C" void kernel_launch(void* const* d_in, const int* in_sizes, int n_in,
                              void* d_out, int out_size)
{
    (void)in_sizes; (void)n_in; (void)out_size;
    const float* z     = (const float*)d_in[0];
    const float* w_ih  = (const float*)d_in[1];
    const float* w_hh  = (const float*)d_in[2];
    const float* b_ih  = (const float*)d_in[3];
    const float* b_hh  = (const float*)d_in[4];
    const float* w_lin = (const float*)d_in[5];
    const float* b_lin = (const float*)d_in[6];
    float* out = (float*)d_out;

    lstm_persistent<<<NBLK, NTHR>>>(z, w_ih, w_hh, b_ih, b_hh, w_lin, b_lin, out);
}

// round 12
// speedup vs baseline: 1.1574x; 1.1574x over previous
#include <cuda_runtime.h>
#include <math.h>

// LSTM autoregressive decoder, B=256, H=1024, I=1, O=512, T=512.
// Single persistent kernel, software grid barriers (2/step).
// fp32 via packed fma.rn.f32x2 (FFMA2) over the k dimension.
// Thread tile phase A: 2j x 4gates x 4b  -> 4 LDS.128 per warp per 4k.

#define BATCH  256
#define HID    1024
#define OUTF   512
#define TSTEPS 512
#define NBLK   128
#define NTHR   256

__device__ __align__(16) float g_h[2][BATCH * HID];
__device__ unsigned long long g_part[BATCH][16];   // packed argmax partials per o-tile
__device__ int g_count;
__device__ unsigned g_sense;

__device__ __forceinline__ void gridbar(unsigned sense_val) {
    __threadfence();
    __syncthreads();
    if (threadIdx.x == 0) {
        if (atomicAdd(&g_count, 1) == NBLK - 1) {
            atomicExch(&g_count, 0);
            __threadfence();
            atomicExch(&g_sense, sense_val ^ 1);
        } else {
            while (*(volatile unsigned*)&g_sense == sense_val) __nanosleep(32);
        }
    }
    __syncthreads();
}

__device__ __forceinline__ float sigf(float x) { return 1.f / (1.f + expf(-x)); }

__device__ __forceinline__ unsigned long long fma2(unsigned long long a,
                                                   unsigned long long b,
                                                   unsigned long long c) {
    unsigned long long d;
    asm("fma.rn.f32x2 %0, %1, %2, %3;" : "=l"(d) : "l"(a), "l"(b), "l"(c));
    return d;
}
__device__ __forceinline__ float lo32(unsigned long long a) {
    return __uint_as_float((unsigned)a);
}
__device__ __forceinline__ float hi32(unsigned long long a) {
    return __uint_as_float((unsigned)(a >> 32));
}

__global__ __launch_bounds__(NTHR, 1)
void lstm_persistent(const float* __restrict__ z,
                     const float* __restrict__ w_ih,
                     const float* __restrict__ w_hh,
                     const float* __restrict__ b_ih,
                     const float* __restrict__ b_hh,
                     const float* __restrict__ w_lin,
                     const float* __restrict__ b_lin,
                     float* __restrict__ out)
{
    // 16 KB staging pool, layout [kkg 0..31][b 0..31][kl 0..3] (words).
    __shared__ __align__(16) float pool[4096];
    __shared__ float xin_s[32];

    const int blk = blockIdx.x;
    const int t   = threadIdx.x;

    // ----- Phase A identity: 16 j-tiles(64) x 8 b-tiles(32) -----
    const int jt  = blk & 15;
    const int btA = blk >> 4;
    const int bg  = t & 7;          // 8 batch groups; b = bg + 8i
    const int jl  = t >> 3;         // 0..31; thread j's: jl and jl+32

    const float* wA[4][2];
    float biasA[4][2], wihA[4][2];
#pragma unroll
    for (int g = 0; g < 4; g++)
#pragma unroll
        for (int jj = 0; jj < 2; jj++) {
            int row = (g << 10) + (jt << 6) + jl + (jj << 5);
            wA[g][jj]   = w_hh + (size_t)row * HID;
            biasA[g][jj] = b_ih[row] + b_hh[row];
            wihA[g][jj]  = w_ih[row];
        }

    // ----- Phase B identity: 16 o-tiles(32) x 8 b-tiles(32) -----
    const int otB = blk & 15;
    const int btB = blk >> 4;
    const int og  = t & 7;          // o = otB*32 + oo*8 + og
    const int bB  = t >> 3;         // 0..31
    const int bGB = (btB << 5) + bB;

    const float* wB[4];
    float blv[4];
    int oIdx[4];
#pragma unroll
    for (int oo = 0; oo < 4; oo++) {
        int o = (otB << 5) + (oo << 3) + og;
        oIdx[oo] = o;
        wB[oo]  = w_lin + (size_t)o * HID;
        blv[oo] = b_lin[o];
    }

    float c_reg[2][4];
#pragma unroll
    for (int jj = 0; jj < 2; jj++)
#pragma unroll
        for (int i = 0; i < 4; i++) c_reg[jj][i] = 0.f;

    unsigned sense = *(volatile unsigned*)&g_sense;

    for (int s = 0; s < TSTEPS; s++) {
        const float* __restrict__ hin = (s == 0) ? z : g_h[(s + 1) & 1];
        float* __restrict__ hout = g_h[s & 1];

        // xin for this block's 32 batch rows from previous step's partials
        if (t < 32) {
            float x = 0.f;
            if (s > 0) {
                const unsigned long long* p = g_part[(btA << 5) + t];
                unsigned long long k = __ldcg(&p[0]);
#pragma unroll
                for (int q = 1; q < 16; q++) {
                    unsigned long long kq = __ldcg(&p[q]);
                    if (kq > k) k = kq;
                }
                x = (float)(0xFFFFFFFFu - (unsigned)(k & 0xFFFFFFFFull));
            }
            xin_s[t] = x;
        }

        // ---------------- Phase A: gates GEMM (f32x2) ----------------
        unsigned long long acc[4][2][4];
#pragma unroll
        for (int g = 0; g < 4; g++)
#pragma unroll
            for (int jj = 0; jj < 2; jj++)
#pragma unroll
                for (int i = 0; i < 4; i++) acc[g][jj][i] = 0ull;

        for (int kc = 0; kc < HID; kc += 128) {
            __syncthreads();
            // stage 32b x 128k into [kkg][b*4] layout
#pragma unroll
            for (int r = 0; r < 4; r++) {
                int idx = r * 256 + t;
                int bb = idx & 31, kkg = idx >> 5;
                *(float4*)&pool[(kkg << 7) + (bb << 2)] =
                    __ldcg((const float4*)(hin + (size_t)((btA << 5) + bb) * HID + kc + (kkg << 2)));
            }
            __syncthreads();

#pragma unroll 4
            for (int kkg = 0; kkg < 32; kkg++) {
                ulonglong2 hv[4];
#pragma unroll
                for (int i = 0; i < 4; i++)
                    hv[i] = *(const ulonglong2*)&pool[(kkg << 7) + ((bg + (i << 3)) << 2)];
#pragma unroll
                for (int g = 0; g < 4; g++)
#pragma unroll
                    for (int jj = 0; jj < 2; jj++) {
                        ulonglong2 wv = *(const ulonglong2*)(wA[g][jj] + kc + (kkg << 2));
#pragma unroll
                        for (int i = 0; i < 4; i++) {
                            acc[g][jj][i] = fma2(wv.x, hv[i].x, acc[g][jj][i]);
                            acc[g][jj][i] = fma2(wv.y, hv[i].y, acc[g][jj][i]);
                        }
                    }
            }
        }

        // ---------------- Cell update (gates fused per thread) ----------------
#pragma unroll
        for (int jj = 0; jj < 2; jj++)
#pragma unroll
            for (int i = 0; i < 4; i++) {
                float xv = xin_s[bg + (i << 3)];
                float pre[4];
#pragma unroll
                for (int g = 0; g < 4; g++) {
                    unsigned long long a = acc[g][jj][i];
                    pre[g] = lo32(a) + hi32(a) + biasA[g][jj] + xv * wihA[g][jj];
                }
                float cn = sigf(pre[1]) * c_reg[jj][i] + sigf(pre[0]) * tanhf(pre[2]);
                float hn = sigf(pre[3]) * tanhf(cn);
                c_reg[jj][i] = cn;
                int b = (btA << 5) + bg + (i << 3);
                hout[(size_t)b * HID + (jt << 6) + jl + (jj << 5)] = hn;
            }

        gridbar(sense); sense ^= 1;   // h_new visible everywhere

        // ---------------- Phase B: head GEMM + logits + argmax ----------------
        unsigned long long acc2[4] = {0ull, 0ull, 0ull, 0ull};

        for (int kc = 0; kc < HID; kc += 128) {
            __syncthreads();
#pragma unroll
            for (int r = 0; r < 4; r++) {
                int idx = r * 256 + t;
                int bb = idx & 31, kkg = idx >> 5;
                *(float4*)&pool[(kkg << 7) + (bb << 2)] =
                    __ldcg((const float4*)(hout + (size_t)((btB << 5) + bb) * HID + kc + (kkg << 2)));
            }
            __syncthreads();

#pragma unroll 4
            for (int kkg = 0; kkg < 32; kkg++) {
                ulonglong2 hv = *(const ulonglong2*)&pool[(kkg << 7) + (bB << 2)];
#pragma unroll
                for (int oo = 0; oo < 4; oo++) {
                    ulonglong2 wv = *(const ulonglong2*)(wB[oo] + kc + (kkg << 2));
                    acc2[oo] = fma2(wv.x, hv.x, acc2[oo]);
                    acc2[oo] = fma2(wv.y, hv.y, acc2[oo]);
                }
            }
        }

        {
            size_t obase = (size_t)bGB * (TSTEPS * OUTF) + (size_t)s * OUTF;
            unsigned long long best = 0ull;
#pragma unroll
            for (int oo = 0; oo < 4; oo++) {
                float v = lo32(acc2[oo]) + hi32(acc2[oo]) + blv[oo];
                out[obase + oIdx[oo]] = v;
                unsigned u = __float_as_uint(v);
                u = (u & 0x80000000u) ? ~u : (u | 0x80000000u);   // order-preserving
                unsigned long long key = ((unsigned long long)u << 32)
                                       | (unsigned long long)(0xFFFFFFFFu - (unsigned)oIdx[oo]);
                if (key > best) best = key;
            }
            // reduce across the 8 og lanes of this b (lanes differ only in low 3 bits)
#pragma unroll
            for (int off = 1; off < 8; off <<= 1) {
                unsigned long long ok = __shfl_xor_sync(0xffffffffu, best, off);
                if (ok > best) best = ok;
            }
            if (og == 0) g_part[bGB][otB] = best;
        }

        gridbar(sense); sense ^= 1;   // argmax partials visible
    }
}

extern "C" void kernel_launch(void* const* d_in, const int* in_sizes, int n_in,
                              void* d_out, int out_size)
{
    (void)in_sizes; (void)n_in; (void)out_size;
    const float* z     = (const float*)d_in[0];
    const float* w_ih  = (const float*)d_in[1];
    const float* w_hh  = (const float*)d_in[2];
    const float* b_ih  = (const float*)d_in[3];
    const float* b_hh  = (const float*)d_in[4];
    const float* w_lin = (const float*)d_in[5];
    const float* b_lin = (const float*)d_in[6];
    float* out = (float*)d_out;

    lstm_persistent<<<NBLK, NTHR>>>(z, w_ih, w_hh, b_ih, b_hh, w_lin, b_lin, out);
}